// round 5
// baseline (speedup 1.0000x reference)
#include <cuda_runtime.h>

#define HID 128
#define OUTD 100
#define NSTEPS 64
#define NP1 (NSTEPS + 1)
#define B2 4096
#define SPB 16                     // samples per block (one per warp)
#define THREADS 512
#define STEP_TILES 4
#define STEPS_PER_TILE (NSTEPS / STEP_TILES)
#define NSB (B2 / SPB)             // 256 sample-groups

// Deterministic partial sums: [step_tile][sample]
__device__ float g_partial[STEP_TILES * B2];

__device__ __forceinline__ float tanh_fast(float x) {
    // accurate tanh via exp-based form; ~1e-6 rel err, saturates correctly
    float e = __expf(2.0f * x);
    return 1.0f - __fdividef(2.0f, e + 1.0f);
}

__global__ __launch_bounds__(THREADS, 1)
void bsde_main(const float* __restrict__ W1, const float* __restrict__ b1,
               const float* __restrict__ W2, const float* __restrict__ b2,
               const float* __restrict__ W3, const float* __restrict__ b3,
               const float* __restrict__ W4, const float* __restrict__ b4,
               const int*   __restrict__ sn, const float* __restrict__ ss,
               const float* __restrict__ sdB, const float* __restrict__ tptr)
{
    extern __shared__ float smem[];
    float* sW2  = smem;                    // 128*128
    float* sW3  = sW2 + HID * HID;         // 128*128
    float* sW4T = sW3 + HID * HID;         // 100*128 (transposed: [n][k])
    float* sw1s = sW4T + OUTD * HID;       // 128
    float* sw1t = sw1s + HID;              // 128
    float* sb1  = sw1t + HID;              // 128
    float* sb2  = sb1 + HID;               // 128
    float* sb3  = sb2 + HID;               // 128
    float* sb4  = sb3 + HID;               // 128 (100 used)
    float* sh   = sb4 + HID;               // SPB * HID * 4 (h,h',h'',pad)

    const int tid = threadIdx.x;

    for (int i = tid; i < HID * HID; i += THREADS) { sW2[i] = W2[i]; sW3[i] = W3[i]; }
    for (int i = tid; i < OUTD * HID; i += THREADS) {
        int n = i >> 7;            // / HID
        int k = i & (HID - 1);
        sW4T[i] = W4[k * OUTD + n];
    }
    if (tid < HID) {
        sw1s[tid] = W1[tid];
        sw1t[tid] = W1[HID + tid];
        sb1[tid]  = b1[tid];
        sb2[tid]  = b2[tid];
        sb3[tid]  = b3[tid];
        sb4[tid]  = (tid < OUTD) ? b4[tid] : 0.0f;
    }
    __syncthreads();

    const int st   = blockIdx.x % STEP_TILES;
    const int sg   = blockIdx.x / STEP_TILES;
    const int w    = tid >> 5;
    const int lane = tid & 31;
    const int b    = sg * SPB + w;
    float* shw = sh + w * (HID * 4);
    const int c0 = lane * 4;

    const float t      = *tptr;
    const float dt     = t / (float)NSTEPS;
    const float halfdt = 0.5f * dt;

    // per-lane layer-1 constants for this lane's 4 hidden columns
    float w1sr[4], w1tr[4], b1r[4], b2r[4], b3r[4];
#pragma unroll
    for (int m = 0; m < 4; m++) {
        w1sr[m] = sw1s[c0 + m];
        w1tr[m] = sw1t[c0 + m];
        b1r[m]  = sb1[c0 + m];
        b2r[m]  = sb2[c0 + m];
        b3r[m]  = sb3[c0 + m];
    }

    const int j0 = st * STEPS_PER_TILE;
    float acc = 0.0f;

    // prefetch step inputs (broadcast loads, overlapped with compute)
    float s_nxt  = ss[b * NP1 + (NSTEPS - j0)];
    int   n_nxt  = sn[b * NP1 + (NSTEPS - j0)];
    float dB_nxt = sdB[b * NSTEPS + (NSTEPS - 1 - j0)];

    for (int jj = 0; jj < STEPS_PER_TILE; ++jj) {
        const int j = j0 + jj;
        const float s  = s_nxt;
        const int   n  = n_nxt;
        const float dB = dB_nxt;
        if (jj + 1 < STEPS_PER_TILE) {
            s_nxt  = ss[b * NP1 + (NSTEPS - (j + 1))];
            n_nxt  = sn[b * NP1 + (NSTEPS - (j + 1))];
            dB_nxt = sdB[b * NSTEPS + (NSTEPS - 1 - (j + 1))];
        }
        // scan carry semantics: j=0 evaluated at tk=t, j>=1 at t - dt*(j-1)
        const float tk = (j == 0) ? t : (t - dt * (float)(j - 1));

        // ---- layer 1 (analytic forward-mode in s) ----
        float hv[4], hd[4], hdd[4];
#pragma unroll
        for (int m = 0; m < 4; m++) {
            float z = fmaf(s, w1sr[m], fmaf(tk, w1tr[m], b1r[m]));
            float h = tanh_fast(z);
            float g = 1.0f - h * h;
            hv[m]  = h;
            hd[m]  = g * w1sr[m];
            hdd[m] = -2.0f * h * hd[m] * w1sr[m];
        }
        __syncwarp();
#pragma unroll
        for (int m = 0; m < 4; m++)
            *(float4*)&shw[(c0 + m) * 4] = make_float4(hv[m], hd[m], hdd[m], 0.0f);
        __syncwarp();

        // ---- layer 2: z = h@W2, zp = h'@W2, zpp = h''@W2 ----
        float z[4], zp[4], zpp[4];
#pragma unroll
        for (int m = 0; m < 4; m++) { z[m] = b2r[m]; zp[m] = 0.0f; zpp[m] = 0.0f; }
#pragma unroll 8
        for (int k = 0; k < HID; k++) {
            float4 hh = *(const float4*)&shw[k * 4];          // broadcast
            float4 wv = *(const float4*)&sW2[k * HID + c0];   // conflict-free
            z[0] = fmaf(hh.x, wv.x, z[0]); zp[0] = fmaf(hh.y, wv.x, zp[0]); zpp[0] = fmaf(hh.z, wv.x, zpp[0]);
            z[1] = fmaf(hh.x, wv.y, z[1]); zp[1] = fmaf(hh.y, wv.y, zp[1]); zpp[1] = fmaf(hh.z, wv.y, zpp[1]);
            z[2] = fmaf(hh.x, wv.z, z[2]); zp[2] = fmaf(hh.y, wv.z, zp[2]); zpp[2] = fmaf(hh.z, wv.z, zpp[2]);
            z[3] = fmaf(hh.x, wv.w, z[3]); zp[3] = fmaf(hh.y, wv.w, zp[3]); zpp[3] = fmaf(hh.z, wv.w, zpp[3]);
        }
        __syncwarp();
#pragma unroll
        for (int m = 0; m < 4; m++) {
            float h = tanh_fast(z[m]);
            float g = 1.0f - h * h;
            hv[m]  = h;
            hd[m]  = g * zp[m];
            hdd[m] = fmaf(g, zpp[m], -2.0f * h * hd[m] * zp[m]);
            *(float4*)&shw[(c0 + m) * 4] = make_float4(hv[m], hd[m], hdd[m], 0.0f);
        }
        __syncwarp();

        // ---- layer 3 ----
#pragma unroll
        for (int m = 0; m < 4; m++) { z[m] = b3r[m]; zp[m] = 0.0f; zpp[m] = 0.0f; }
#pragma unroll 8
        for (int k = 0; k < HID; k++) {
            float4 hh = *(const float4*)&shw[k * 4];
            float4 wv = *(const float4*)&sW3[k * HID + c0];
            z[0] = fmaf(hh.x, wv.x, z[0]); zp[0] = fmaf(hh.y, wv.x, zp[0]); zpp[0] = fmaf(hh.z, wv.x, zpp[0]);
            z[1] = fmaf(hh.x, wv.y, z[1]); zp[1] = fmaf(hh.y, wv.y, zp[1]); zpp[1] = fmaf(hh.z, wv.y, zpp[1]);
            z[2] = fmaf(hh.x, wv.z, z[2]); zp[2] = fmaf(hh.y, wv.z, zp[2]); zpp[2] = fmaf(hh.z, wv.z, zpp[2]);
            z[3] = fmaf(hh.x, wv.w, z[3]); zp[3] = fmaf(hh.y, wv.w, zp[3]); zpp[3] = fmaf(hh.z, wv.w, zpp[3]);
        }
#pragma unroll
        for (int m = 0; m < 4; m++) {
            float h = tanh_fast(z[m]);
            float g = 1.0f - h * h;
            hv[m]  = h;
            hd[m]  = g * zp[m];
            hdd[m] = fmaf(g, zpp[m], -2.0f * h * hd[m] * zp[m]);
        }

        // ---- layer 4: dot with column n of W4 (registers) ----
        float4 wv4 = *(const float4*)&sW4T[n * HID + c0];
        float pu  = hv[0] * wv4.x + hv[1] * wv4.y + hv[2] * wv4.z + hv[3] * wv4.w;
        float pp  = hd[0] * wv4.x + hd[1] * wv4.y + hd[2] * wv4.z + hd[3] * wv4.w;
        float ppp = hdd[0] * wv4.x + hdd[1] * wv4.y + hdd[2] * wv4.z + hdd[3] * wv4.w;
#pragma unroll
        for (int off = 16; off >= 1; off >>= 1) {
            pu  += __shfl_xor_sync(0xffffffffu, pu,  off);
            pp  += __shfl_xor_sync(0xffffffffu, pp,  off);
            ppp += __shfl_xor_sync(0xffffffffu, ppp, off);
        }

        float contrib = -fmaf(pp, dB, ppp * halfdt);   // -(ps*dB + pss*dt/2)
        if (j == 0) contrib += pu + sb4[n];            // terminal value term
        acc += contrib;
    }

    if (lane == 0) g_partial[st * B2 + b] = acc;
}

__global__ void bsde_final(const float* __restrict__ ss, float* __restrict__ out)
{
    int b = blockIdx.x * blockDim.x + threadIdx.x;
    if (b >= B2) return;
    float u = 0.0f;
#pragma unroll
    for (int st = 0; st < STEP_TILES; st++) u += g_partial[st * B2 + b];
    out[b] = u;
    // u0 = sqrt(beta/(2pi)) * exp(-beta*s0^2/2) / out_dim,  beta = 1e6
    float s0 = ss[b * NP1];
    out[B2 + b] = 3.9894228040143274f * expf(-500000.0f * (s0 * s0));
}

extern "C" void kernel_launch(void* const* d_in, const int* in_sizes, int n_in,
                              void* d_out, int out_size)
{
    const float* W1   = (const float*)d_in[0];
    const float* b1   = (const float*)d_in[1];
    const float* W2   = (const float*)d_in[2];
    const float* b2   = (const float*)d_in[3];
    const float* W3   = (const float*)d_in[4];
    const float* b3   = (const float*)d_in[5];
    const float* W4   = (const float*)d_in[6];
    const float* b4   = (const float*)d_in[7];
    const int*   sn   = (const int*)d_in[8];
    const float* ss   = (const float*)d_in[9];
    const float* sdB  = (const float*)d_in[10];
    const float* tptr = (const float*)d_in[11];
    float* out = (float*)d_out;

    size_t smem_bytes = (size_t)(2 * HID * HID + OUTD * HID + 6 * HID + SPB * HID * 4) * sizeof(float);
    cudaFuncSetAttribute(bsde_main, cudaFuncAttributeMaxDynamicSharedMemorySize, (int)smem_bytes);

    bsde_main<<<NSB * STEP_TILES, THREADS, smem_bytes>>>(W1, b1, W2, b2, W3, b3, W4, b4,
                                                         sn, ss, sdB, tptr);
    bsde_final<<<(B2 + 255) / 256, 256>>>(ss, out);
}

// round 8
// speedup vs baseline: 4.5813x; 4.5813x over previous
#include <cuda_runtime.h>
#include <cuda_fp16.h>
#include <cstdint>

#define NSTEPS 64
#define NP1 65
#define B2 4096
#define TILE 64
#define THREADS 256
#define SPC 4
#define GROUPS (NSTEPS / SPC)     // 16
#define NTILES (B2 / TILE)        // 64

// ---- smem byte offsets (total exactly 232448 = 227KB) ----
#define OFF_W2HI 0
#define OFF_W2LO 32768
#define OFF_W3HI 65536
#define OFF_W3LO 98304
#define OFF_A0H  131072
#define OFF_A0D  147456
#define OFF_A0E  163840
#define OFF_A1H  180224
#define OFF_A1D  196608
#define OFF_A1E  212992
#define OFF_B2   229376
#define OFF_B3   229888
#define OFF_B4   230400
#define OFF_S    230912
#define OFF_DB   231168
#define OFF_NB   231424
#define OFF_SRED 231680
#define SMEM_BYTES 232448

#define IB2   (OFF_B2 >> 2)
#define IB3   (OFF_B3 >> 2)
#define IB4   (OFF_B4 >> 2)
#define IS    (OFF_S >> 2)
#define IDB   (OFF_DB >> 2)
#define ISRED (OFF_SRED >> 2)

__device__ float g_partial[GROUPS * B2];
__device__ float g_W4T[100 * 128];

static __device__ __forceinline__ float tanh_fast(float x) {
    float e = __expf(2.0f * x);
    return 1.0f - __fdividef(2.0f, e + 1.0f);
}
// swizzled byte offset for [rows x 128] fp16 tile with 256B rows:
// XOR row%8 into the 16B-chunk index bits -> conflict-free ldmatrix
static __device__ __forceinline__ uint32_t swzb(uint32_t r, uint32_t cb) {
    return ((r << 8) + cb) ^ ((r & 7) << 4);
}
static __device__ __forceinline__ uint32_t packh2(float lo, float hi) {
    uint32_t r; asm("cvt.rn.f16x2.f32 %0,%1,%2;" : "=r"(r) : "f"(hi), "f"(lo)); return r;
}
static __device__ __forceinline__ void ldsm4(uint32_t* r, uint32_t a) {
    asm volatile("ldmatrix.sync.aligned.m8n8.x4.shared.b16 {%0,%1,%2,%3},[%4];"
        : "=r"(r[0]), "=r"(r[1]), "=r"(r[2]), "=r"(r[3]) : "r"(a));
}
static __device__ __forceinline__ void ldsm2(uint32_t* r, uint32_t a) {
    asm volatile("ldmatrix.sync.aligned.m8n8.x2.shared.b16 {%0,%1},[%2];"
        : "=r"(r[0]), "=r"(r[1]) : "r"(a));
}
static __device__ __forceinline__ void mma16816(float* d, const uint32_t* a, const uint32_t* b) {
    asm volatile("mma.sync.aligned.m16n8k16.row.col.f32.f16.f16.f32 "
        "{%0,%1,%2,%3},{%4,%5,%6,%7},{%8,%9},{%0,%1,%2,%3};"
        : "+f"(d[0]), "+f"(d[1]), "+f"(d[2]), "+f"(d[3])
        : "r"(a[0]), "r"(a[1]), "r"(a[2]), "r"(a[3]), "r"(b[0]), "r"(b[1]));
}
static __device__ __forceinline__ void chain(float z, float p, float q,
                                             float& h, float& d, float& e) {
    h = tanh_fast(z);
    float g = 1.0f - h * h;
    d = g * p;
    e = fmaf(g, q, -2.0f * h * d * p);
}

__global__ void w4t_init(const float* __restrict__ W4) {
    int i = blockIdx.x * 256 + threadIdx.x;
    if (i < 12800) {
        int n = i >> 7, k = i & 127;
        g_W4T[i] = W4[k * 100 + n];
    }
}

__global__ __launch_bounds__(THREADS, 1)
void bsde_main(const float* __restrict__ W1, const float* __restrict__ b1,
               const float* __restrict__ W2, const float* __restrict__ b2f,
               const float* __restrict__ W3, const float* __restrict__ b3f,
               const float* __restrict__ b4f,
               const int* __restrict__ sn, const float* __restrict__ ss,
               const float* __restrict__ sdB, const float* __restrict__ tptr)
{
    extern __shared__ char smem[];
    uint32_t sb = (uint32_t)__cvta_generic_to_shared(smem);
    float* smf = (float*)smem;
    int* snb = (int*)(smem + OFF_NB);
    const int tid = threadIdx.x;
    const int lane = tid & 31;
    const int w = tid >> 5;
    const int wq = w & 3;          // row slab
    const int nh = w >> 2;         // col half
    const int m0 = wq * 16;
    const int nbase = nh * 64;

    // ---- preload weights: WT[j][k] fp16 hi + residual lo, swizzled ----
    for (int i = tid; i < 128 * 128; i += THREADS) {
        int k = i >> 7, j = i & 127;
        uint32_t o = swzb((uint32_t)j, (uint32_t)(k * 2));
        float v = W2[i];
        __half h = __float2half_rn(v);
        *(__half*)(smem + OFF_W2HI + o) = h;
        *(__half*)(smem + OFF_W2LO + o) = __float2half_rn(v - __half2float(h));
        v = W3[i];
        h = __float2half_rn(v);
        *(__half*)(smem + OFF_W3HI + o) = h;
        *(__half*)(smem + OFF_W3LO + o) = __float2half_rn(v - __half2float(h));
    }
    if (tid < 128) {
        smf[IB2 + tid] = b2f[tid];
        smf[IB3 + tid] = b3f[tid];
        smf[IB4 + tid] = (tid < 100) ? b4f[tid] : 0.0f;
    }
    __syncthreads();

    const int tile = blockIdx.x & (NTILES - 1);
    const int grp = blockIdx.x >> 6;
    const int j0 = grp * SPC;
    const float t = *tptr;
    const float dt = t / (float)NSTEPS;
    const float halfdt = 0.5f * dt;
    float acc = 0.0f;

    // per-thread ldmatrix address components.
    // A (x4): lanes 0-7 rows m0..m0+7 k0-7; 8-15 rows+8 k0-7; 16-23 rows k8-15; 24-31 rows+8 k8-15
    const uint32_t rowA = (uint32_t)(m0 + (lane & 7) + ((lane >> 3) & 1) * 8);
    const uint32_t colA = (uint32_t)(((lane >> 4) & 1) * 16);   // byte col within k16 step
    const uint32_t rbA  = rowA << 8;                             // row base bytes
    const uint32_t xA   = (rowA & 7) << 4;                       // swizzle XOR
    // B (x2): lanes 0-7 rows n0.., k0-7; lanes 8-15 rows n0.., k8-15
    const int lb = lane & 15;
    const uint32_t rowB = (uint32_t)(lb & 7);
    const uint32_t colB = (uint32_t)(((lb >> 3) & 1) * 16);
    const uint32_t xB   = rowB << 4;

    const int r1 = m0 + (lane >> 2);
    const int r2 = r1 + 8;
    const int jc = 2 * (lane & 3);

    for (int jj = 0; jj < SPC; jj++) {
        const int j = j0 + jj;
        if (tid < TILE) {
            int bidx = tile * TILE + tid;
            smf[IS + tid] = ss[bidx * NP1 + (NSTEPS - j)];
            smf[IDB + tid] = sdB[bidx * NSTEPS + (NSTEPS - 1 - j)];
            snb[tid] = sn[bidx * NP1 + (NSTEPS - j)];
        }
        __syncthreads();
        const float tk = (j == 0) ? t : (t - dt * (float)(j - 1));

        // ---- layer 1 (scalar forward-mode) -> A0 fp16 ----
        for (int i = tid; i < TILE * 64; i += THREADS) {
            int r = i >> 6, c0 = (i & 63) * 2;
            float s = smf[IS + r];
            float2 w1s = __ldg((const float2*)&W1[c0]);
            float2 w1t = __ldg((const float2*)&W1[128 + c0]);
            float2 b1v = __ldg((const float2*)&b1[c0]);
            float z0 = fmaf(s, w1s.x, fmaf(tk, w1t.x, b1v.x));
            float z1 = fmaf(s, w1s.y, fmaf(tk, w1t.y, b1v.y));
            float h0 = tanh_fast(z0), h1 = tanh_fast(z1);
            float g0 = 1.f - h0 * h0, g1 = 1.f - h1 * h1;
            float d0 = g0 * w1s.x, d1 = g1 * w1s.y;
            float e0 = -2.f * h0 * d0 * w1s.x, e1 = -2.f * h1 * d1 * w1s.y;
            uint32_t o = swzb((uint32_t)r, (uint32_t)(c0 * 2));
            *(uint32_t*)(smem + OFF_A0H + o) = packh2(h0, h1);
            *(uint32_t*)(smem + OFF_A0D + o) = packh2(d0, d1);
            *(uint32_t*)(smem + OFF_A0E + o) = packh2(e0, e1);
        }
        __syncthreads();

        // ================= layer 2: A0 @ W2 -> A1 =================
        for (int nt = 0; nt < 4; nt++) {
            const int n0 = nbase + nt * 16;
            const int j0c = n0 + jc;
            float2 bj = *(const float2*)&smf[IB2 + j0c];
            float2 bj8 = *(const float2*)&smf[IB2 + j0c + 8];
            float dz[8], dp[8] = {0, 0, 0, 0, 0, 0, 0, 0}, dq[8] = {0, 0, 0, 0, 0, 0, 0, 0};
            dz[0] = bj.x; dz[1] = bj.y; dz[2] = bj.x; dz[3] = bj.y;
            dz[4] = bj8.x; dz[5] = bj8.y; dz[6] = bj8.x; dz[7] = bj8.y;
            const uint32_t aHb = sb + OFF_A0H + rbA, aDb = sb + OFF_A0D + rbA, aEb = sb + OFF_A0E + rbA;
            const uint32_t bhaB = sb + OFF_W2HI + (((uint32_t)n0 + rowB) << 8);
            const uint32_t bhbB = sb + OFF_W2HI + (((uint32_t)(n0 + 8) + rowB) << 8);
            const uint32_t blaB = sb + OFF_W2LO + (((uint32_t)n0 + rowB) << 8);
            const uint32_t blbB = sb + OFF_W2LO + (((uint32_t)(n0 + 8) + rowB) << 8);
#pragma unroll
            for (int k = 0; k < 8; k++) {
                const uint32_t oA = (colA + 32u * k) ^ xA;     // swizzle recomputed per k
                const uint32_t oB = (colB + 32u * k) ^ xB;
                uint32_t fa[4], fd[4], fe[4], ba[2], bb[2], la[2], lbv[2];
                ldsm4(fa, aHb + oA); ldsm4(fd, aDb + oA); ldsm4(fe, aEb + oA);
                ldsm2(ba, bhaB + oB); ldsm2(bb, bhbB + oB);
                ldsm2(la, blaB + oB); ldsm2(lbv, blbB + oB);
                mma16816(dz, fa, ba); mma16816(dz, fa, la);
                mma16816(dz + 4, fa, bb); mma16816(dz + 4, fa, lbv);
                mma16816(dp, fd, ba); mma16816(dp, fd, la);
                mma16816(dp + 4, fd, bb); mma16816(dp + 4, fd, lbv);
                mma16816(dq, fe, ba); mma16816(dq, fe, la);
                mma16816(dq + 4, fe, bb); mma16816(dq + 4, fe, lbv);
            }
            float h[8], hd[8], he[8];
#pragma unroll
            for (int e = 0; e < 8; e++) chain(dz[e], dp[e], dq[e], h[e], hd[e], he[e]);
            uint32_t o1 = swzb((uint32_t)r1, (uint32_t)(j0c * 2));
            uint32_t o2 = swzb((uint32_t)r2, (uint32_t)(j0c * 2));
            uint32_t o3 = swzb((uint32_t)r1, (uint32_t)((j0c + 8) * 2));
            uint32_t o4 = swzb((uint32_t)r2, (uint32_t)((j0c + 8) * 2));
            *(uint32_t*)(smem + OFF_A1H + o1) = packh2(h[0], h[1]);
            *(uint32_t*)(smem + OFF_A1H + o2) = packh2(h[2], h[3]);
            *(uint32_t*)(smem + OFF_A1H + o3) = packh2(h[4], h[5]);
            *(uint32_t*)(smem + OFF_A1H + o4) = packh2(h[6], h[7]);
            *(uint32_t*)(smem + OFF_A1D + o1) = packh2(hd[0], hd[1]);
            *(uint32_t*)(smem + OFF_A1D + o2) = packh2(hd[2], hd[3]);
            *(uint32_t*)(smem + OFF_A1D + o3) = packh2(hd[4], hd[5]);
            *(uint32_t*)(smem + OFF_A1D + o4) = packh2(hd[6], hd[7]);
            *(uint32_t*)(smem + OFF_A1E + o1) = packh2(he[0], he[1]);
            *(uint32_t*)(smem + OFF_A1E + o2) = packh2(he[2], he[3]);
            *(uint32_t*)(smem + OFF_A1E + o3) = packh2(he[4], he[5]);
            *(uint32_t*)(smem + OFF_A1E + o4) = packh2(he[6], he[7]);
        }
        __syncthreads();

        // ================= layer 3 (A1 @ W3) fused with layer 4 =================
        const int nb1 = snb[r1], nb2 = snb[r2];
        const float* w4r1 = g_W4T + nb1 * 128;
        const float* w4r2 = g_W4T + nb2 * 128;
        float pu1 = 0.f, pp1 = 0.f, pq1 = 0.f, pu2 = 0.f, pp2 = 0.f, pq2 = 0.f;
        for (int nt = 0; nt < 4; nt++) {
            const int n0 = nbase + nt * 16;
            const int j0c = n0 + jc;
            float2 bj = *(const float2*)&smf[IB3 + j0c];
            float2 bj8 = *(const float2*)&smf[IB3 + j0c + 8];
            float dz[8], dp[8] = {0, 0, 0, 0, 0, 0, 0, 0}, dq[8] = {0, 0, 0, 0, 0, 0, 0, 0};
            dz[0] = bj.x; dz[1] = bj.y; dz[2] = bj.x; dz[3] = bj.y;
            dz[4] = bj8.x; dz[5] = bj8.y; dz[6] = bj8.x; dz[7] = bj8.y;
            const uint32_t aHb = sb + OFF_A1H + rbA, aDb = sb + OFF_A1D + rbA, aEb = sb + OFF_A1E + rbA;
            const uint32_t bhaB = sb + OFF_W3HI + (((uint32_t)n0 + rowB) << 8);
            const uint32_t bhbB = sb + OFF_W3HI + (((uint32_t)(n0 + 8) + rowB) << 8);
            const uint32_t blaB = sb + OFF_W3LO + (((uint32_t)n0 + rowB) << 8);
            const uint32_t blbB = sb + OFF_W3LO + (((uint32_t)(n0 + 8) + rowB) << 8);
#pragma unroll
            for (int k = 0; k < 8; k++) {
                const uint32_t oA = (colA + 32u * k) ^ xA;
                const uint32_t oB = (colB + 32u * k) ^ xB;
                uint32_t fa[4], fd[4], fe[4], ba[2], bb[2], la[2], lbv[2];
                ldsm4(fa, aHb + oA); ldsm4(fd, aDb + oA); ldsm4(fe, aEb + oA);
                ldsm2(ba, bhaB + oB); ldsm2(bb, bhbB + oB);
                ldsm2(la, blaB + oB); ldsm2(lbv, blbB + oB);
                mma16816(dz, fa, ba); mma16816(dz, fa, la);
                mma16816(dz + 4, fa, bb); mma16816(dz + 4, fa, lbv);
                mma16816(dp, fd, ba); mma16816(dp, fd, la);
                mma16816(dp + 4, fd, bb); mma16816(dp + 4, fd, lbv);
                mma16816(dq, fe, ba); mma16816(dq, fe, la);
                mma16816(dq + 4, fe, bb); mma16816(dq + 4, fe, lbv);
            }
            float h[8], hd[8], he[8];
#pragma unroll
            for (int e = 0; e < 8; e++) chain(dz[e], dp[e], dq[e], h[e], hd[e], he[e]);
            float2 wa1 = __ldg((const float2*)&w4r1[j0c]);
            float2 wb1 = __ldg((const float2*)&w4r1[j0c + 8]);
            float2 wa2 = __ldg((const float2*)&w4r2[j0c]);
            float2 wb2 = __ldg((const float2*)&w4r2[j0c + 8]);
            pu1 += h[0] * wa1.x + h[1] * wa1.y + h[4] * wb1.x + h[5] * wb1.y;
            pp1 += hd[0] * wa1.x + hd[1] * wa1.y + hd[4] * wb1.x + hd[5] * wb1.y;
            pq1 += he[0] * wa1.x + he[1] * wa1.y + he[4] * wb1.x + he[5] * wb1.y;
            pu2 += h[2] * wa2.x + h[3] * wa2.y + h[6] * wb2.x + h[7] * wb2.y;
            pp2 += hd[2] * wa2.x + hd[3] * wa2.y + hd[6] * wb2.x + hd[7] * wb2.y;
            pq2 += he[2] * wa2.x + he[3] * wa2.y + he[6] * wb2.x + he[7] * wb2.y;
        }
        // reduce across the 4 lanes sharing each row pair
#pragma unroll
        for (int off = 1; off <= 2; off <<= 1) {
            pu1 += __shfl_xor_sync(0xffffffffu, pu1, off);
            pp1 += __shfl_xor_sync(0xffffffffu, pp1, off);
            pq1 += __shfl_xor_sync(0xffffffffu, pq1, off);
            pu2 += __shfl_xor_sync(0xffffffffu, pu2, off);
            pp2 += __shfl_xor_sync(0xffffffffu, pp2, off);
            pq2 += __shfl_xor_sync(0xffffffffu, pq2, off);
        }
        if ((lane & 3) == 0) {
            float dB1 = smf[IDB + r1], dB2 = smf[IDB + r2];
            float c1 = -fmaf(pp1, dB1, pq1 * halfdt);
            float c2 = -fmaf(pp2, dB2, pq2 * halfdt);
            if (j == 0) {
                c1 += pu1 + (nh == 0 ? smf[IB4 + nb1] : 0.f);
                c2 += pu2 + (nh == 0 ? smf[IB4 + nb2] : 0.f);
            }
            smf[ISRED + r1 * 2 + nh] = c1;
            smf[ISRED + r2 * 2 + nh] = c2;
        }
        __syncthreads();
        if (tid < TILE) acc += smf[ISRED + tid * 2] + smf[ISRED + tid * 2 + 1];
        __syncthreads();
    }

    if (tid < TILE) g_partial[grp * B2 + tile * TILE + tid] = acc;
}

__global__ void bsde_final(const float* __restrict__ ss, float* __restrict__ out)
{
    int b = blockIdx.x * 256 + threadIdx.x;
    if (b >= B2) return;
    float u = 0.0f;
#pragma unroll
    for (int g = 0; g < GROUPS; g++) u += g_partial[g * B2 + b];
    out[b] = u;
    float s0 = ss[b * NP1];
    out[B2 + b] = 3.9894228040143274f * expf(-500000.0f * (s0 * s0));
}

extern "C" void kernel_launch(void* const* d_in, const int* in_sizes, int n_in,
                              void* d_out, int out_size)
{
    const float* W1 = (const float*)d_in[0];
    const float* b1 = (const float*)d_in[1];
    const float* W2 = (const float*)d_in[2];
    const float* b2 = (const float*)d_in[3];
    const float* W3 = (const float*)d_in[4];
    const float* b3 = (const float*)d_in[5];
    const float* W4 = (const float*)d_in[6];
    const float* b4 = (const float*)d_in[7];
    const int* sn = (const int*)d_in[8];
    const float* ss = (const float*)d_in[9];
    const float* sdB = (const float*)d_in[10];
    const float* tptr = (const float*)d_in[11];
    float* out = (float*)d_out;

    cudaFuncSetAttribute(bsde_main, cudaFuncAttributeMaxDynamicSharedMemorySize, SMEM_BYTES);

    w4t_init<<<50, 256>>>(W4);
    bsde_main<<<NTILES * GROUPS, THREADS, SMEM_BYTES>>>(W1, b1, W2, b2, W3, b3, b4,
                                                        sn, ss, sdB, tptr);
    bsde_final<<<16, 256>>>(ss, out);
}

// round 9
// speedup vs baseline: 5.9055x; 1.2890x over previous
#include <cuda_runtime.h>
#include <cuda_fp16.h>
#include <cstdint>

#define NSTEPS 64
#define NP1 65
#define B2 4096
#define TILE 64
#define THREADS 256
#define SPC 4
#define GROUPS (NSTEPS / SPC)     // 16
#define NTILES (B2 / TILE)        // 64

// ---- smem byte offsets ----
#define OFF_W2HI 0
#define OFF_W3HI 32768
#define OFF_A0H  65536
#define OFF_A0D  81920
#define OFF_A0E  98304
#define OFF_A1H  114688
#define OFF_A1D  131072
#define OFF_A1E  147456
#define OFF_B2   163840
#define OFF_B3   164352
#define OFF_B4   164864
#define OFF_S    165376
#define OFF_DB   165632
#define OFF_NB   165888
#define OFF_SRED 166144
#define SMEM_BYTES 166912

#define IB2   (OFF_B2 >> 2)
#define IB3   (OFF_B3 >> 2)
#define IB4   (OFF_B4 >> 2)
#define IS    (OFF_S >> 2)
#define IDB   (OFF_DB >> 2)
#define ISRED (OFF_SRED >> 2)

__device__ float g_partial[GROUPS * B2];
__device__ float g_W4T[100 * 128];

static __device__ __forceinline__ float tanh_fast(float x) {
    float e = __expf(2.0f * x);
    return 1.0f - __fdividef(2.0f, e + 1.0f);
}
// swizzled byte offset for [rows x 128] fp16 tile with 256B rows:
// XOR row%8 into the 16B-chunk index bits -> conflict-free ldmatrix
static __device__ __forceinline__ uint32_t swzb(uint32_t r, uint32_t cb) {
    return ((r << 8) + cb) ^ ((r & 7) << 4);
}
static __device__ __forceinline__ uint32_t packh2(float lo, float hi) {
    uint32_t r; asm("cvt.rn.f16x2.f32 %0,%1,%2;" : "=r"(r) : "f"(hi), "f"(lo)); return r;
}
static __device__ __forceinline__ void ldsm4(uint32_t* r, uint32_t a) {
    asm volatile("ldmatrix.sync.aligned.m8n8.x4.shared.b16 {%0,%1,%2,%3},[%4];"
        : "=r"(r[0]), "=r"(r[1]), "=r"(r[2]), "=r"(r[3]) : "r"(a));
}
static __device__ __forceinline__ void ldsm2(uint32_t* r, uint32_t a) {
    asm volatile("ldmatrix.sync.aligned.m8n8.x2.shared.b16 {%0,%1},[%2];"
        : "=r"(r[0]), "=r"(r[1]) : "r"(a));
}
static __device__ __forceinline__ void mma16816(float* d, const uint32_t* a, const uint32_t* b) {
    asm volatile("mma.sync.aligned.m16n8k16.row.col.f32.f16.f16.f32 "
        "{%0,%1,%2,%3},{%4,%5,%6,%7},{%8,%9},{%0,%1,%2,%3};"
        : "+f"(d[0]), "+f"(d[1]), "+f"(d[2]), "+f"(d[3])
        : "r"(a[0]), "r"(a[1]), "r"(a[2]), "r"(a[3]), "r"(b[0]), "r"(b[1]));
}
static __device__ __forceinline__ void chain(float z, float p, float q,
                                             float& h, float& d, float& e) {
    h = tanh_fast(z);
    float g = 1.0f - h * h;
    d = g * p;
    e = fmaf(g, q, -2.0f * h * d * p);
}

__global__ void w4t_init(const float* __restrict__ W4) {
    int i = blockIdx.x * 256 + threadIdx.x;
    if (i < 12800) {
        int n = i >> 7, k = i & 127;
        g_W4T[i] = W4[k * 100 + n];
    }
}

__global__ __launch_bounds__(THREADS, 1)
void bsde_main(const float* __restrict__ W1, const float* __restrict__ b1,
               const float* __restrict__ W2, const float* __restrict__ b2f,
               const float* __restrict__ W3, const float* __restrict__ b3f,
               const float* __restrict__ b4f,
               const int* __restrict__ sn, const float* __restrict__ ss,
               const float* __restrict__ sdB, const float* __restrict__ tptr)
{
    extern __shared__ char smem[];
    uint32_t sb = (uint32_t)__cvta_generic_to_shared(smem);
    float* smf = (float*)smem;
    int* snb = (int*)(smem + OFF_NB);
    const int tid = threadIdx.x;
    const int lane = tid & 31;
    const int w = tid >> 5;
    const int wq = w & 3;          // row slab
    const int nh = w >> 2;         // col half
    const int m0 = wq * 16;
    const int nbase = nh * 64;

    // ---- preload weights: WT[j][k] fp16, swizzled ----
    for (int i = tid; i < 128 * 128; i += THREADS) {
        int k = i >> 7, j = i & 127;
        uint32_t o = swzb((uint32_t)j, (uint32_t)(k * 2));
        *(__half*)(smem + OFF_W2HI + o) = __float2half_rn(W2[i]);
        *(__half*)(smem + OFF_W3HI + o) = __float2half_rn(W3[i]);
    }
    if (tid < 128) {
        smf[IB2 + tid] = b2f[tid];
        smf[IB3 + tid] = b3f[tid];
        smf[IB4 + tid] = (tid < 100) ? b4f[tid] : 0.0f;
    }
    __syncthreads();

    const int tile = blockIdx.x & (NTILES - 1);
    const int grp = blockIdx.x >> 6;
    const int j0 = grp * SPC;
    const float t = *tptr;
    const float dt = t / (float)NSTEPS;
    const float halfdt = 0.5f * dt;
    float acc = 0.0f;

    // per-thread ldmatrix address components
    const uint32_t rowA = (uint32_t)(m0 + (lane & 7) + ((lane >> 3) & 1) * 8);
    const uint32_t colA = (uint32_t)(((lane >> 4) & 1) * 16);
    const uint32_t rbA  = rowA << 8;
    const uint32_t xA   = (rowA & 7) << 4;
    const int lb = lane & 15;
    const uint32_t rowB = (uint32_t)(lb & 7);
    const uint32_t colB = (uint32_t)(((lb >> 3) & 1) * 16);
    const uint32_t xB   = rowB << 4;

    const int r1 = m0 + (lane >> 2);
    const int r2 = r1 + 8;
    const int jc = 2 * (lane & 3);

    for (int jj = 0; jj < SPC; jj++) {
        const int j = j0 + jj;
        if (tid < TILE) {
            int bidx = tile * TILE + tid;
            smf[IS + tid] = ss[bidx * NP1 + (NSTEPS - j)];
            smf[IDB + tid] = sdB[bidx * NSTEPS + (NSTEPS - 1 - j)];
            snb[tid] = sn[bidx * NP1 + (NSTEPS - j)];
        }
        __syncthreads();
        const float tk = (j == 0) ? t : (t - dt * (float)(j - 1));

        // ---- layer 1 (scalar forward-mode) -> A0 fp16 ----
        for (int i = tid; i < TILE * 64; i += THREADS) {
            int r = i >> 6, c0 = (i & 63) * 2;
            float s = smf[IS + r];
            float2 w1s = __ldg((const float2*)&W1[c0]);
            float2 w1t = __ldg((const float2*)&W1[128 + c0]);
            float2 b1v = __ldg((const float2*)&b1[c0]);
            float z0 = fmaf(s, w1s.x, fmaf(tk, w1t.x, b1v.x));
            float z1 = fmaf(s, w1s.y, fmaf(tk, w1t.y, b1v.y));
            float h0 = tanh_fast(z0), h1 = tanh_fast(z1);
            float g0 = 1.f - h0 * h0, g1 = 1.f - h1 * h1;
            float d0 = g0 * w1s.x, d1 = g1 * w1s.y;
            float e0 = -2.f * h0 * d0 * w1s.x, e1 = -2.f * h1 * d1 * w1s.y;
            uint32_t o = swzb((uint32_t)r, (uint32_t)(c0 * 2));
            *(uint32_t*)(smem + OFF_A0H + o) = packh2(h0, h1);
            *(uint32_t*)(smem + OFF_A0D + o) = packh2(d0, d1);
            *(uint32_t*)(smem + OFF_A0E + o) = packh2(e0, e1);
        }
        __syncthreads();

        // ================= layer 2: A0 @ W2 -> A1 =================
        for (int nt = 0; nt < 4; nt++) {
            const int n0 = nbase + nt * 16;
            const int j0c = n0 + jc;
            float2 bj = *(const float2*)&smf[IB2 + j0c];
            float2 bj8 = *(const float2*)&smf[IB2 + j0c + 8];
            float dz[8], dp[8] = {0, 0, 0, 0, 0, 0, 0, 0}, dq[8] = {0, 0, 0, 0, 0, 0, 0, 0};
            dz[0] = bj.x; dz[1] = bj.y; dz[2] = bj.x; dz[3] = bj.y;
            dz[4] = bj8.x; dz[5] = bj8.y; dz[6] = bj8.x; dz[7] = bj8.y;
            const uint32_t aHb = sb + OFF_A0H + rbA, aDb = sb + OFF_A0D + rbA, aEb = sb + OFF_A0E + rbA;
            const uint32_t bhaB = sb + OFF_W2HI + (((uint32_t)n0 + rowB) << 8);
            const uint32_t bhbB = sb + OFF_W2HI + (((uint32_t)(n0 + 8) + rowB) << 8);
#pragma unroll
            for (int k = 0; k < 8; k++) {
                const uint32_t oA = (colA + 32u * k) ^ xA;
                const uint32_t oB = (colB + 32u * k) ^ xB;
                uint32_t fa[4], fd[4], fe[4], ba[2], bb[2];
                ldsm4(fa, aHb + oA); ldsm4(fd, aDb + oA); ldsm4(fe, aEb + oA);
                ldsm2(ba, bhaB + oB); ldsm2(bb, bhbB + oB);
                mma16816(dz, fa, ba); mma16816(dz + 4, fa, bb);
                mma16816(dp, fd, ba); mma16816(dp + 4, fd, bb);
                mma16816(dq, fe, ba); mma16816(dq + 4, fe, bb);
            }
            float h[8], hd[8], he[8];
#pragma unroll
            for (int e = 0; e < 8; e++) chain(dz[e], dp[e], dq[e], h[e], hd[e], he[e]);
            uint32_t o1 = swzb((uint32_t)r1, (uint32_t)(j0c * 2));
            uint32_t o2 = swzb((uint32_t)r2, (uint32_t)(j0c * 2));
            uint32_t o3 = swzb((uint32_t)r1, (uint32_t)((j0c + 8) * 2));
            uint32_t o4 = swzb((uint32_t)r2, (uint32_t)((j0c + 8) * 2));
            *(uint32_t*)(smem + OFF_A1H + o1) = packh2(h[0], h[1]);
            *(uint32_t*)(smem + OFF_A1H + o2) = packh2(h[2], h[3]);
            *(uint32_t*)(smem + OFF_A1H + o3) = packh2(h[4], h[5]);
            *(uint32_t*)(smem + OFF_A1H + o4) = packh2(h[6], h[7]);
            *(uint32_t*)(smem + OFF_A1D + o1) = packh2(hd[0], hd[1]);
            *(uint32_t*)(smem + OFF_A1D + o2) = packh2(hd[2], hd[3]);
            *(uint32_t*)(smem + OFF_A1D + o3) = packh2(hd[4], hd[5]);
            *(uint32_t*)(smem + OFF_A1D + o4) = packh2(hd[6], hd[7]);
            *(uint32_t*)(smem + OFF_A1E + o1) = packh2(he[0], he[1]);
            *(uint32_t*)(smem + OFF_A1E + o2) = packh2(he[2], he[3]);
            *(uint32_t*)(smem + OFF_A1E + o3) = packh2(he[4], he[5]);
            *(uint32_t*)(smem + OFF_A1E + o4) = packh2(he[6], he[7]);
        }
        __syncthreads();

        // ================= layer 3 (A1 @ W3) fused with layer 4 =================
        const int nb1 = snb[r1], nb2 = snb[r2];
        const float* w4r1 = g_W4T + nb1 * 128;
        const float* w4r2 = g_W4T + nb2 * 128;
        float pu1 = 0.f, pp1 = 0.f, pq1 = 0.f, pu2 = 0.f, pp2 = 0.f, pq2 = 0.f;
        for (int nt = 0; nt < 4; nt++) {
            const int n0 = nbase + nt * 16;
            const int j0c = n0 + jc;
            float2 bj = *(const float2*)&smf[IB3 + j0c];
            float2 bj8 = *(const float2*)&smf[IB3 + j0c + 8];
            float dz[8], dp[8] = {0, 0, 0, 0, 0, 0, 0, 0}, dq[8] = {0, 0, 0, 0, 0, 0, 0, 0};
            dz[0] = bj.x; dz[1] = bj.y; dz[2] = bj.x; dz[3] = bj.y;
            dz[4] = bj8.x; dz[5] = bj8.y; dz[6] = bj8.x; dz[7] = bj8.y;
            const uint32_t aHb = sb + OFF_A1H + rbA, aDb = sb + OFF_A1D + rbA, aEb = sb + OFF_A1E + rbA;
            const uint32_t bhaB = sb + OFF_W3HI + (((uint32_t)n0 + rowB) << 8);
            const uint32_t bhbB = sb + OFF_W3HI + (((uint32_t)(n0 + 8) + rowB) << 8);
#pragma unroll
            for (int k = 0; k < 8; k++) {
                const uint32_t oA = (colA + 32u * k) ^ xA;
                const uint32_t oB = (colB + 32u * k) ^ xB;
                uint32_t fa[4], fd[4], fe[4], ba[2], bb[2];
                ldsm4(fa, aHb + oA); ldsm4(fd, aDb + oA); ldsm4(fe, aEb + oA);
                ldsm2(ba, bhaB + oB); ldsm2(bb, bhbB + oB);
                mma16816(dz, fa, ba); mma16816(dz + 4, fa, bb);
                mma16816(dp, fd, ba); mma16816(dp + 4, fd, bb);
                mma16816(dq, fe, ba); mma16816(dq + 4, fe, bb);
            }
            float h[8], hd[8], he[8];
#pragma unroll
            for (int e = 0; e < 8; e++) chain(dz[e], dp[e], dq[e], h[e], hd[e], he[e]);
            float2 wa1 = __ldg((const float2*)&w4r1[j0c]);
            float2 wb1 = __ldg((const float2*)&w4r1[j0c + 8]);
            float2 wa2 = __ldg((const float2*)&w4r2[j0c]);
            float2 wb2 = __ldg((const float2*)&w4r2[j0c + 8]);
            pu1 += h[0] * wa1.x + h[1] * wa1.y + h[4] * wb1.x + h[5] * wb1.y;
            pp1 += hd[0] * wa1.x + hd[1] * wa1.y + hd[4] * wb1.x + hd[5] * wb1.y;
            pq1 += he[0] * wa1.x + he[1] * wa1.y + he[4] * wb1.x + he[5] * wb1.y;
            pu2 += h[2] * wa2.x + h[3] * wa2.y + h[6] * wb2.x + h[7] * wb2.y;
            pp2 += hd[2] * wa2.x + hd[3] * wa2.y + hd[6] * wb2.x + hd[7] * wb2.y;
            pq2 += he[2] * wa2.x + he[3] * wa2.y + he[6] * wb2.x + he[7] * wb2.y;
        }
        // reduce across the 4 lanes sharing each row pair
#pragma unroll
        for (int off = 1; off <= 2; off <<= 1) {
            pu1 += __shfl_xor_sync(0xffffffffu, pu1, off);
            pp1 += __shfl_xor_sync(0xffffffffu, pp1, off);
            pq1 += __shfl_xor_sync(0xffffffffu, pq1, off);
            pu2 += __shfl_xor_sync(0xffffffffu, pu2, off);
            pp2 += __shfl_xor_sync(0xffffffffu, pp2, off);
            pq2 += __shfl_xor_sync(0xffffffffu, pq2, off);
        }
        if ((lane & 3) == 0) {
            float dB1 = smf[IDB + r1], dB2 = smf[IDB + r2];
            float c1 = -fmaf(pp1, dB1, pq1 * halfdt);
            float c2 = -fmaf(pp2, dB2, pq2 * halfdt);
            if (j == 0) {
                c1 += pu1 + (nh == 0 ? smf[IB4 + nb1] : 0.f);
                c2 += pu2 + (nh == 0 ? smf[IB4 + nb2] : 0.f);
            }
            smf[ISRED + r1 * 2 + nh] = c1;
            smf[ISRED + r2 * 2 + nh] = c2;
        }
        __syncthreads();
        if (tid < TILE) acc += smf[ISRED + tid * 2] + smf[ISRED + tid * 2 + 1];
        __syncthreads();
    }

    if (tid < TILE) g_partial[grp * B2 + tile * TILE + tid] = acc;
}

__global__ void bsde_final(const float* __restrict__ ss, float* __restrict__ out)
{
    int b = blockIdx.x * 256 + threadIdx.x;
    if (b >= B2) return;
    float u = 0.0f;
#pragma unroll
    for (int g = 0; g < GROUPS; g++) u += g_partial[g * B2 + b];
    out[b] = u;
    float s0 = ss[b * NP1];
    out[B2 + b] = 3.9894228040143274f * expf(-500000.0f * (s0 * s0));
}

extern "C" void kernel_launch(void* const* d_in, const int* in_sizes, int n_in,
                              void* d_out, int out_size)
{
    const float* W1 = (const float*)d_in[0];
    const float* b1 = (const float*)d_in[1];
    const float* W2 = (const float*)d_in[2];
    const float* b2 = (const float*)d_in[3];
    const float* W3 = (const float*)d_in[4];
    const float* b3 = (const float*)d_in[5];
    const float* W4 = (const float*)d_in[6];
    const float* b4 = (const float*)d_in[7];
    const int* sn = (const int*)d_in[8];
    const float* ss = (const float*)d_in[9];
    const float* sdB = (const float*)d_in[10];
    const float* tptr = (const float*)d_in[11];
    float* out = (float*)d_out;

    cudaFuncSetAttribute(bsde_main, cudaFuncAttributeMaxDynamicSharedMemorySize, SMEM_BYTES);

    w4t_init<<<50, 256>>>(W4);
    bsde_main<<<NTILES * GROUPS, THREADS, SMEM_BYTES>>>(W1, b1, W2, b2, W3, b3, b4,
                                                        sn, ss, sdB, tptr);
    bsde_final<<<16, 256>>>(ss, out);
}

// round 10
// speedup vs baseline: 6.5588x; 1.1106x over previous
#include <cuda_runtime.h>
#include <cuda_fp16.h>
#include <cstdint>

#define NSTEPS 64
#define NP1 65
#define B2 4096
#define TILE 64
#define THREADS 256
#define SPC 4
#define GROUPS (NSTEPS / SPC)     // 16
#define NTILES (B2 / TILE)        // 64

// ---- smem byte offsets ----
#define OFF_W2HI 0
#define OFF_W3HI 32768
#define OFF_A0H  65536
#define OFF_A0D  81920
#define OFF_A0E  98304
#define OFF_A1H  114688
#define OFF_A1D  131072
#define OFF_A1E  147456
#define OFF_B2   163840
#define OFF_B3   164352
#define OFF_B4   164864
#define OFF_S    165376
#define OFF_DB   165632
#define OFF_NB   165888
#define OFF_SRED 166144
#define SMEM_BYTES 166912

#define IB2   (OFF_B2 >> 2)
#define IB3   (OFF_B3 >> 2)
#define IB4   (OFF_B4 >> 2)
#define IS    (OFF_S >> 2)
#define IDB   (OFF_DB >> 2)
#define ISRED (OFF_SRED >> 2)

__device__ float g_partial[GROUPS * B2];
__device__ float g_W4T[100 * 128];

static __device__ __forceinline__ float tanh_fast(float x) {
    float e = __expf(2.0f * x);
    return 1.0f - __fdividef(2.0f, e + 1.0f);
}
// swizzled byte offset for [rows x 128] fp16 tile with 256B rows
static __device__ __forceinline__ uint32_t swzb(uint32_t r, uint32_t cb) {
    return ((r << 8) + cb) ^ ((r & 7) << 4);
}
static __device__ __forceinline__ uint32_t packh2(float lo, float hi) {
    uint32_t r; asm("cvt.rn.f16x2.f32 %0,%1,%2;" : "=r"(r) : "f"(hi), "f"(lo)); return r;
}
static __device__ __forceinline__ void ldsm4(uint32_t* r, uint32_t a) {
    asm volatile("ldmatrix.sync.aligned.m8n8.x4.shared.b16 {%0,%1,%2,%3},[%4];"
        : "=r"(r[0]), "=r"(r[1]), "=r"(r[2]), "=r"(r[3]) : "r"(a));
}
static __device__ __forceinline__ void mma16816(float* d, const uint32_t* a, const uint32_t* b) {
    asm volatile("mma.sync.aligned.m16n8k16.row.col.f32.f16.f16.f32 "
        "{%0,%1,%2,%3},{%4,%5,%6,%7},{%8,%9},{%0,%1,%2,%3};"
        : "+f"(d[0]), "+f"(d[1]), "+f"(d[2]), "+f"(d[3])
        : "r"(a[0]), "r"(a[1]), "r"(a[2]), "r"(a[3]), "r"(b[0]), "r"(b[1]));
}
static __device__ __forceinline__ void chain(float z, float p, float q,
                                             float& h, float& d, float& e) {
    h = tanh_fast(z);
    float g = 1.0f - h * h;
    d = g * p;
    e = fmaf(g, q, -2.0f * h * d * p);
}

__global__ void w4t_init(const float* __restrict__ W4) {
    int i = blockIdx.x * 256 + threadIdx.x;
    if (i < 12800) {
        int n = i >> 7, k = i & 127;
        g_W4T[i] = W4[k * 100 + n];
    }
}

__global__ __launch_bounds__(THREADS, 1)
void bsde_main(const float* __restrict__ W1, const float* __restrict__ b1,
               const float* __restrict__ W2, const float* __restrict__ b2f,
               const float* __restrict__ W3, const float* __restrict__ b3f,
               const float* __restrict__ b4f,
               const int* __restrict__ sn, const float* __restrict__ ss,
               const float* __restrict__ sdB, const float* __restrict__ tptr)
{
    extern __shared__ char smem[];
    uint32_t sb = (uint32_t)__cvta_generic_to_shared(smem);
    float* smf = (float*)smem;
    int* snb = (int*)(smem + OFF_NB);
    const int tid = threadIdx.x;
    const int lane = tid & 31;
    const int w = tid >> 5;
    const int wq = w & 3;          // row slab
    const int nh = w >> 2;         // col half
    const int m0 = wq * 16;
    const int nbase = nh * 64;

    // ---- preload weights: WT[j][k] fp16, swizzled ----
    for (int i = tid; i < 128 * 128; i += THREADS) {
        int k = i >> 7, j = i & 127;
        uint32_t o = swzb((uint32_t)j, (uint32_t)(k * 2));
        *(__half*)(smem + OFF_W2HI + o) = __float2half_rn(W2[i]);
        *(__half*)(smem + OFF_W3HI + o) = __float2half_rn(W3[i]);
    }
    if (tid < 128) {
        smf[IB2 + tid] = b2f[tid];
        smf[IB3 + tid] = b3f[tid];
        smf[IB4 + tid] = (tid < 100) ? b4f[tid] : 0.0f;
    }
    __syncthreads();

    const int tile = blockIdx.x & (NTILES - 1);
    const int grp = blockIdx.x >> 6;
    const int j0 = grp * SPC;
    const float t = *tptr;
    const float dt = t / (float)NSTEPS;
    const float halfdt = 0.5f * dt;
    float acc = 0.0f;

    // A-fragment (x4) lane addressing
    const uint32_t rowA = (uint32_t)(m0 + (lane & 7) + ((lane >> 3) & 1) * 8);
    const uint32_t colA = (uint32_t)(((lane >> 4) & 1) * 16);
    const uint32_t rbA  = rowA << 8;
    const uint32_t xA   = (rowA & 7) << 4;
    // B-fragment (x4) lane addressing: groups = [n0-7|k0-7], [n0-7|k8-15], [n8-15|k0-7], [n8-15|k8-15]
    const uint32_t rowB4 = (uint32_t)((lane & 7) + ((lane >> 4) & 1) * 8);
    const uint32_t colB4 = (uint32_t)(((lane >> 3) & 1) * 16);
    const uint32_t xB4   = (uint32_t)(lane & 7) << 4;

    const int r1 = m0 + (lane >> 2);
    const int r2 = r1 + 8;
    const int jc = 2 * (lane & 3);

    for (int jj = 0; jj < SPC; jj++) {
        const int j = j0 + jj;
        if (tid < TILE) {
            int bidx = tile * TILE + tid;
            smf[IS + tid] = ss[bidx * NP1 + (NSTEPS - j)];
            smf[IDB + tid] = sdB[bidx * NSTEPS + (NSTEPS - 1 - j)];
            snb[tid] = sn[bidx * NP1 + (NSTEPS - j)];
        }
        __syncthreads();
        const float tk = (j == 0) ? t : (t - dt * (float)(j - 1));

        // ---- layer 1 (scalar forward-mode) -> A0 fp16 ----
        for (int i = tid; i < TILE * 64; i += THREADS) {
            int r = i >> 6, c0 = (i & 63) * 2;
            float s = smf[IS + r];
            float2 w1s = __ldg((const float2*)&W1[c0]);
            float2 w1t = __ldg((const float2*)&W1[128 + c0]);
            float2 b1v = __ldg((const float2*)&b1[c0]);
            float z0 = fmaf(s, w1s.x, fmaf(tk, w1t.x, b1v.x));
            float z1 = fmaf(s, w1s.y, fmaf(tk, w1t.y, b1v.y));
            float h0 = tanh_fast(z0), h1 = tanh_fast(z1);
            float g0 = 1.f - h0 * h0, g1 = 1.f - h1 * h1;
            float d0 = g0 * w1s.x, d1 = g1 * w1s.y;
            float e0 = -2.f * h0 * d0 * w1s.x, e1 = -2.f * h1 * d1 * w1s.y;
            uint32_t o = swzb((uint32_t)r, (uint32_t)(c0 * 2));
            *(uint32_t*)(smem + OFF_A0H + o) = packh2(h0, h1);
            *(uint32_t*)(smem + OFF_A0D + o) = packh2(d0, d1);
            *(uint32_t*)(smem + OFF_A0E + o) = packh2(e0, e1);
        }
        __syncthreads();

        // ================= layer 2: A0 @ W2 -> A1 (k-outer, nt-inner) =================
        {
            float dz[4][8], dp[4][8], dq[4][8];
#pragma unroll
            for (int nt = 0; nt < 4; nt++) {
                const int j0c = nbase + nt * 16 + jc;
                float2 bj = *(const float2*)&smf[IB2 + j0c];
                float2 bj8 = *(const float2*)&smf[IB2 + j0c + 8];
                dz[nt][0] = bj.x; dz[nt][1] = bj.y; dz[nt][2] = bj.x; dz[nt][3] = bj.y;
                dz[nt][4] = bj8.x; dz[nt][5] = bj8.y; dz[nt][6] = bj8.x; dz[nt][7] = bj8.y;
#pragma unroll
                for (int e = 0; e < 8; e++) { dp[nt][e] = 0.f; dq[nt][e] = 0.f; }
            }
            const uint32_t aHb = sb + OFF_A0H + rbA, aDb = sb + OFF_A0D + rbA, aEb = sb + OFF_A0E + rbA;
            const uint32_t wBase = sb + OFF_W2HI + ((uint32_t)nbase + rowB4 << 8);
#pragma unroll
            for (int k = 0; k < 8; k++) {
                const uint32_t oA = (colA + 32u * k) ^ xA;
                const uint32_t oB = (colB4 + 32u * k) ^ xB4;
                uint32_t fa[4], fd[4], fe[4];
                ldsm4(fa, aHb + oA); ldsm4(fd, aDb + oA); ldsm4(fe, aEb + oA);
#pragma unroll
                for (int nt = 0; nt < 4; nt++) {
                    uint32_t bf[4];
                    ldsm4(bf, wBase + ((uint32_t)(nt * 16) << 8) + oB);
                    mma16816(dz[nt], fa, bf); mma16816(dz[nt] + 4, fa, bf + 2);
                    mma16816(dp[nt], fd, bf); mma16816(dp[nt] + 4, fd, bf + 2);
                    mma16816(dq[nt], fe, bf); mma16816(dq[nt] + 4, fe, bf + 2);
                }
            }
#pragma unroll
            for (int nt = 0; nt < 4; nt++) {
                const int j0c = nbase + nt * 16 + jc;
                float h[8], hd[8], he[8];
#pragma unroll
                for (int e = 0; e < 8; e++) chain(dz[nt][e], dp[nt][e], dq[nt][e], h[e], hd[e], he[e]);
                uint32_t o1 = swzb((uint32_t)r1, (uint32_t)(j0c * 2));
                uint32_t o2 = swzb((uint32_t)r2, (uint32_t)(j0c * 2));
                uint32_t o3 = swzb((uint32_t)r1, (uint32_t)((j0c + 8) * 2));
                uint32_t o4 = swzb((uint32_t)r2, (uint32_t)((j0c + 8) * 2));
                *(uint32_t*)(smem + OFF_A1H + o1) = packh2(h[0], h[1]);
                *(uint32_t*)(smem + OFF_A1H + o2) = packh2(h[2], h[3]);
                *(uint32_t*)(smem + OFF_A1H + o3) = packh2(h[4], h[5]);
                *(uint32_t*)(smem + OFF_A1H + o4) = packh2(h[6], h[7]);
                *(uint32_t*)(smem + OFF_A1D + o1) = packh2(hd[0], hd[1]);
                *(uint32_t*)(smem + OFF_A1D + o2) = packh2(hd[2], hd[3]);
                *(uint32_t*)(smem + OFF_A1D + o3) = packh2(hd[4], hd[5]);
                *(uint32_t*)(smem + OFF_A1D + o4) = packh2(hd[6], hd[7]);
                *(uint32_t*)(smem + OFF_A1E + o1) = packh2(he[0], he[1]);
                *(uint32_t*)(smem + OFF_A1E + o2) = packh2(he[2], he[3]);
                *(uint32_t*)(smem + OFF_A1E + o3) = packh2(he[4], he[5]);
                *(uint32_t*)(smem + OFF_A1E + o4) = packh2(he[6], he[7]);
            }
        }
        __syncthreads();

        // ================= layer 3 (A1 @ W3, k-outer) fused with layer 4 =================
        {
            float dz[4][8], dp[4][8], dq[4][8];
#pragma unroll
            for (int nt = 0; nt < 4; nt++) {
                const int j0c = nbase + nt * 16 + jc;
                float2 bj = *(const float2*)&smf[IB3 + j0c];
                float2 bj8 = *(const float2*)&smf[IB3 + j0c + 8];
                dz[nt][0] = bj.x; dz[nt][1] = bj.y; dz[nt][2] = bj.x; dz[nt][3] = bj.y;
                dz[nt][4] = bj8.x; dz[nt][5] = bj8.y; dz[nt][6] = bj8.x; dz[nt][7] = bj8.y;
#pragma unroll
                for (int e = 0; e < 8; e++) { dp[nt][e] = 0.f; dq[nt][e] = 0.f; }
            }
            const uint32_t aHb = sb + OFF_A1H + rbA, aDb = sb + OFF_A1D + rbA, aEb = sb + OFF_A1E + rbA;
            const uint32_t wBase = sb + OFF_W3HI + ((uint32_t)nbase + rowB4 << 8);
#pragma unroll
            for (int k = 0; k < 8; k++) {
                const uint32_t oA = (colA + 32u * k) ^ xA;
                const uint32_t oB = (colB4 + 32u * k) ^ xB4;
                uint32_t fa[4], fd[4], fe[4];
                ldsm4(fa, aHb + oA); ldsm4(fd, aDb + oA); ldsm4(fe, aEb + oA);
#pragma unroll
                for (int nt = 0; nt < 4; nt++) {
                    uint32_t bf[4];
                    ldsm4(bf, wBase + ((uint32_t)(nt * 16) << 8) + oB);
                    mma16816(dz[nt], fa, bf); mma16816(dz[nt] + 4, fa, bf + 2);
                    mma16816(dp[nt], fd, bf); mma16816(dp[nt] + 4, fd, bf + 2);
                    mma16816(dq[nt], fe, bf); mma16816(dq[nt] + 4, fe, bf + 2);
                }
            }
            const int nb1 = snb[r1], nb2 = snb[r2];
            const float* w4r1 = g_W4T + nb1 * 128;
            const float* w4r2 = g_W4T + nb2 * 128;
            float pu1 = 0.f, pp1 = 0.f, pq1 = 0.f, pu2 = 0.f, pp2 = 0.f, pq2 = 0.f;
#pragma unroll
            for (int nt = 0; nt < 4; nt++) {
                const int j0c = nbase + nt * 16 + jc;
                float h[8], hd[8], he[8];
#pragma unroll
                for (int e = 0; e < 8; e++) chain(dz[nt][e], dp[nt][e], dq[nt][e], h[e], hd[e], he[e]);
                float2 wa1 = __ldg((const float2*)&w4r1[j0c]);
                float2 wb1 = __ldg((const float2*)&w4r1[j0c + 8]);
                float2 wa2 = __ldg((const float2*)&w4r2[j0c]);
                float2 wb2 = __ldg((const float2*)&w4r2[j0c + 8]);
                pu1 += h[0] * wa1.x + h[1] * wa1.y + h[4] * wb1.x + h[5] * wb1.y;
                pp1 += hd[0] * wa1.x + hd[1] * wa1.y + hd[4] * wb1.x + hd[5] * wb1.y;
                pq1 += he[0] * wa1.x + he[1] * wa1.y + he[4] * wb1.x + he[5] * wb1.y;
                pu2 += h[2] * wa2.x + h[3] * wa2.y + h[6] * wb2.x + h[7] * wb2.y;
                pp2 += hd[2] * wa2.x + hd[3] * wa2.y + hd[6] * wb2.x + hd[7] * wb2.y;
                pq2 += he[2] * wa2.x + he[3] * wa2.y + he[6] * wb2.x + he[7] * wb2.y;
            }
            // reduce across the 4 lanes sharing each row pair
#pragma unroll
            for (int off = 1; off <= 2; off <<= 1) {
                pu1 += __shfl_xor_sync(0xffffffffu, pu1, off);
                pp1 += __shfl_xor_sync(0xffffffffu, pp1, off);
                pq1 += __shfl_xor_sync(0xffffffffu, pq1, off);
                pu2 += __shfl_xor_sync(0xffffffffu, pu2, off);
                pp2 += __shfl_xor_sync(0xffffffffu, pp2, off);
                pq2 += __shfl_xor_sync(0xffffffffu, pq2, off);
            }
            if ((lane & 3) == 0) {
                float dB1 = smf[IDB + r1], dB2 = smf[IDB + r2];
                float c1 = -fmaf(pp1, dB1, pq1 * halfdt);
                float c2 = -fmaf(pp2, dB2, pq2 * halfdt);
                if (j == 0) {
                    c1 += pu1 + (nh == 0 ? smf[IB4 + nb1] : 0.f);
                    c2 += pu2 + (nh == 0 ? smf[IB4 + nb2] : 0.f);
                }
                smf[ISRED + r1 * 2 + nh] = c1;
                smf[ISRED + r2 * 2 + nh] = c2;
            }
        }
        __syncthreads();
        if (tid < TILE) acc += smf[ISRED + tid * 2] + smf[ISRED + tid * 2 + 1];
        __syncthreads();
    }

    if (tid < TILE) g_partial[grp * B2 + tile * TILE + tid] = acc;
}

__global__ void bsde_final(const float* __restrict__ ss, float* __restrict__ out)
{
    int b = blockIdx.x * 256 + threadIdx.x;
    if (b >= B2) return;
    float u = 0.0f;
#pragma unroll
    for (int g = 0; g < GROUPS; g++) u += g_partial[g * B2 + b];
    out[b] = u;
    float s0 = ss[b * NP1];
    out[B2 + b] = 3.9894228040143274f * expf(-500000.0f * (s0 * s0));
}

extern "C" void kernel_launch(void* const* d_in, const int* in_sizes, int n_in,
                              void* d_out, int out_size)
{
    const float* W1 = (const float*)d_in[0];
    const float* b1 = (const float*)d_in[1];
    const float* W2 = (const float*)d_in[2];
    const float* b2 = (const float*)d_in[3];
    const float* W3 = (const float*)d_in[4];
    const float* b3 = (const float*)d_in[5];
    const float* W4 = (const float*)d_in[6];
    const float* b4 = (const float*)d_in[7];
    const int* sn = (const int*)d_in[8];
    const float* ss = (const float*)d_in[9];
    const float* sdB = (const float*)d_in[10];
    const float* tptr = (const float*)d_in[11];
    float* out = (float*)d_out;

    cudaFuncSetAttribute(bsde_main, cudaFuncAttributeMaxDynamicSharedMemorySize, SMEM_BYTES);

    w4t_init<<<50, 256>>>(W4);
    bsde_main<<<NTILES * GROUPS, THREADS, SMEM_BYTES>>>(W1, b1, W2, b2, W3, b3, b4,
                                                        sn, ss, sdB, tptr);
    bsde_final<<<16, 256>>>(ss, out);
}

// round 11
// speedup vs baseline: 7.4049x; 1.1290x over previous
#include <cuda_runtime.h>
#include <cuda_fp16.h>
#include <cstdint>

#define NSTEPS 64
#define NP1 65
#define B2 4096
#define TILE 64
#define THREADS 512
#define SPC 4
#define GROUPS (NSTEPS / SPC)     // 16
#define NTILES (B2 / TILE)        // 64

// ---- smem byte offsets ----
#define OFF_W2HI 0
#define OFF_W3HI 32768
#define OFF_A0H  65536
#define OFF_A0D  81920
#define OFF_A0E  98304
#define OFF_A1H  114688
#define OFF_A1D  131072
#define OFF_A1E  147456
#define OFF_B2   163840
#define OFF_B3   164352
#define OFF_B4   164864
#define OFF_S    165376
#define OFF_DB   165632
#define OFF_NB   165888
#define OFF_SRED 166144
#define SMEM_BYTES 167424

#define IB2   (OFF_B2 >> 2)
#define IB3   (OFF_B3 >> 2)
#define IB4   (OFF_B4 >> 2)
#define IS    (OFF_S >> 2)
#define IDB   (OFF_DB >> 2)
#define ISRED (OFF_SRED >> 2)

__device__ float g_partial[GROUPS * B2];
__device__ float g_W4T[100 * 128];

static __device__ __forceinline__ float tanh_fast(float x) {
    float e = __expf(2.0f * x);
    return 1.0f - __fdividef(2.0f, e + 1.0f);
}
// swizzled byte offset for [rows x 128] fp16 tile with 256B rows
static __device__ __forceinline__ uint32_t swzb(uint32_t r, uint32_t cb) {
    return ((r << 8) + cb) ^ ((r & 7) << 4);
}
static __device__ __forceinline__ uint32_t packh2(float lo, float hi) {
    uint32_t r; asm("cvt.rn.f16x2.f32 %0,%1,%2;" : "=r"(r) : "f"(hi), "f"(lo)); return r;
}
static __device__ __forceinline__ void ldsm4(uint32_t* r, uint32_t a) {
    asm volatile("ldmatrix.sync.aligned.m8n8.x4.shared.b16 {%0,%1,%2,%3},[%4];"
        : "=r"(r[0]), "=r"(r[1]), "=r"(r[2]), "=r"(r[3]) : "r"(a));
}
static __device__ __forceinline__ void mma16816(float* d, const uint32_t* a, const uint32_t* b) {
    asm volatile("mma.sync.aligned.m16n8k16.row.col.f32.f16.f16.f32 "
        "{%0,%1,%2,%3},{%4,%5,%6,%7},{%8,%9},{%0,%1,%2,%3};"
        : "+f"(d[0]), "+f"(d[1]), "+f"(d[2]), "+f"(d[3])
        : "r"(a[0]), "r"(a[1]), "r"(a[2]), "r"(a[3]), "r"(b[0]), "r"(b[1]));
}
static __device__ __forceinline__ void chain(float z, float p, float q,
                                             float& h, float& d, float& e) {
    h = tanh_fast(z);
    float g = 1.0f - h * h;
    d = g * p;
    e = fmaf(g, q, -2.0f * h * d * p);
}

__global__ void w4t_init(const float* __restrict__ W4) {
    int i = blockIdx.x * 256 + threadIdx.x;
    if (i < 12800) {
        int n = i >> 7, k = i & 127;
        g_W4T[i] = W4[k * 100 + n];
    }
}

__global__ __launch_bounds__(THREADS, 1)
void bsde_main(const float* __restrict__ W1, const float* __restrict__ b1,
               const float* __restrict__ W2, const float* __restrict__ b2f,
               const float* __restrict__ W3, const float* __restrict__ b3f,
               const float* __restrict__ b4f,
               const int* __restrict__ sn, const float* __restrict__ ss,
               const float* __restrict__ sdB, const float* __restrict__ tptr)
{
    extern __shared__ char smem[];
    uint32_t sb = (uint32_t)__cvta_generic_to_shared(smem);
    float* smf = (float*)smem;
    int* snb = (int*)(smem + OFF_NB);
    const int tid = threadIdx.x;
    const int lane = tid & 31;
    const int w = tid >> 5;        // 16 warps
    const int wq = w & 3;          // row slab (m16)
    const int nq = w >> 2;         // col quarter (n32)
    const int m0 = wq * 16;
    const int nbase = nq * 32;

    // ---- preload weights: WT[j][k] fp16, swizzled ----
    for (int i = tid; i < 128 * 128; i += THREADS) {
        int k = i >> 7, j = i & 127;
        uint32_t o = swzb((uint32_t)j, (uint32_t)(k * 2));
        *(__half*)(smem + OFF_W2HI + o) = __float2half_rn(W2[i]);
        *(__half*)(smem + OFF_W3HI + o) = __float2half_rn(W3[i]);
    }
    if (tid < 128) {
        smf[IB2 + tid] = b2f[tid];
        smf[IB3 + tid] = b3f[tid];
        smf[IB4 + tid] = (tid < 100) ? b4f[tid] : 0.0f;
    }
    __syncthreads();

    const int tile = blockIdx.x & (NTILES - 1);
    const int grp = blockIdx.x >> 6;
    const int j0 = grp * SPC;
    const float t = *tptr;
    const float dt = t / (float)NSTEPS;
    const float halfdt = 0.5f * dt;
    float acc = 0.0f;

    // A-fragment (x4) lane addressing
    const uint32_t rowA = (uint32_t)(m0 + (lane & 7) + ((lane >> 3) & 1) * 8);
    const uint32_t colA = (uint32_t)(((lane >> 4) & 1) * 16);
    const uint32_t rbA  = rowA << 8;
    const uint32_t xA   = (rowA & 7) << 4;
    // B-fragment (x4) lane addressing: [n0-7|k0-7],[n0-7|k8-15],[n8-15|k0-7],[n8-15|k8-15]
    const uint32_t rowB4 = (uint32_t)((lane & 7) + ((lane >> 4) & 1) * 8);
    const uint32_t colB4 = (uint32_t)(((lane >> 3) & 1) * 16);
    const uint32_t xB4   = (uint32_t)(lane & 7) << 4;

    const int r1 = m0 + (lane >> 2);
    const int r2 = r1 + 8;
    const int jc = 2 * (lane & 3);

    for (int jj = 0; jj < SPC; jj++) {
        const int j = j0 + jj;
        if (tid < TILE) {
            int bidx = tile * TILE + tid;
            smf[IS + tid] = ss[bidx * NP1 + (NSTEPS - j)];
            smf[IDB + tid] = sdB[bidx * NSTEPS + (NSTEPS - 1 - j)];
            snb[tid] = sn[bidx * NP1 + (NSTEPS - j)];
        }
        __syncthreads();
        const float tk = (j == 0) ? t : (t - dt * (float)(j - 1));

        // ---- layer 1 (scalar forward-mode) -> A0 fp16 ----
        for (int i = tid; i < TILE * 64; i += THREADS) {
            int r = i >> 6, c0 = (i & 63) * 2;
            float s = smf[IS + r];
            float2 w1s = __ldg((const float2*)&W1[c0]);
            float2 w1t = __ldg((const float2*)&W1[128 + c0]);
            float2 b1v = __ldg((const float2*)&b1[c0]);
            float z0 = fmaf(s, w1s.x, fmaf(tk, w1t.x, b1v.x));
            float z1 = fmaf(s, w1s.y, fmaf(tk, w1t.y, b1v.y));
            float h0 = tanh_fast(z0), h1 = tanh_fast(z1);
            float g0 = 1.f - h0 * h0, g1 = 1.f - h1 * h1;
            float d0 = g0 * w1s.x, d1 = g1 * w1s.y;
            float e0 = -2.f * h0 * d0 * w1s.x, e1 = -2.f * h1 * d1 * w1s.y;
            uint32_t o = swzb((uint32_t)r, (uint32_t)(c0 * 2));
            *(uint32_t*)(smem + OFF_A0H + o) = packh2(h0, h1);
            *(uint32_t*)(smem + OFF_A0D + o) = packh2(d0, d1);
            *(uint32_t*)(smem + OFF_A0E + o) = packh2(e0, e1);
        }
        __syncthreads();

        // ================= layer 2: A0 @ W2 -> A1 (k-outer, nt-inner) =================
        {
            float dz[2][8], dp[2][8], dq[2][8];
#pragma unroll
            for (int nt = 0; nt < 2; nt++) {
                const int j0c = nbase + nt * 16 + jc;
                float2 bj = *(const float2*)&smf[IB2 + j0c];
                float2 bj8 = *(const float2*)&smf[IB2 + j0c + 8];
                dz[nt][0] = bj.x; dz[nt][1] = bj.y; dz[nt][2] = bj.x; dz[nt][3] = bj.y;
                dz[nt][4] = bj8.x; dz[nt][5] = bj8.y; dz[nt][6] = bj8.x; dz[nt][7] = bj8.y;
#pragma unroll
                for (int e = 0; e < 8; e++) { dp[nt][e] = 0.f; dq[nt][e] = 0.f; }
            }
            const uint32_t aHb = sb + OFF_A0H + rbA, aDb = sb + OFF_A0D + rbA, aEb = sb + OFF_A0E + rbA;
            const uint32_t wBase = sb + OFF_W2HI + (((uint32_t)nbase + rowB4) << 8);
#pragma unroll
            for (int k = 0; k < 8; k++) {
                const uint32_t oA = (colA + 32u * k) ^ xA;
                const uint32_t oB = (colB4 + 32u * k) ^ xB4;
                uint32_t fa[4], fd[4], fe[4];
                ldsm4(fa, aHb + oA); ldsm4(fd, aDb + oA); ldsm4(fe, aEb + oA);
#pragma unroll
                for (int nt = 0; nt < 2; nt++) {
                    uint32_t bf[4];
                    ldsm4(bf, wBase + ((uint32_t)(nt * 16) << 8) + oB);
                    mma16816(dz[nt], fa, bf); mma16816(dz[nt] + 4, fa, bf + 2);
                    mma16816(dp[nt], fd, bf); mma16816(dp[nt] + 4, fd, bf + 2);
                    mma16816(dq[nt], fe, bf); mma16816(dq[nt] + 4, fe, bf + 2);
                }
            }
#pragma unroll
            for (int nt = 0; nt < 2; nt++) {
                const int j0c = nbase + nt * 16 + jc;
                float h[8], hd[8], he[8];
#pragma unroll
                for (int e = 0; e < 8; e++) chain(dz[nt][e], dp[nt][e], dq[nt][e], h[e], hd[e], he[e]);
                uint32_t o1 = swzb((uint32_t)r1, (uint32_t)(j0c * 2));
                uint32_t o2 = swzb((uint32_t)r2, (uint32_t)(j0c * 2));
                uint32_t o3 = swzb((uint32_t)r1, (uint32_t)((j0c + 8) * 2));
                uint32_t o4 = swzb((uint32_t)r2, (uint32_t)((j0c + 8) * 2));
                *(uint32_t*)(smem + OFF_A1H + o1) = packh2(h[0], h[1]);
                *(uint32_t*)(smem + OFF_A1H + o2) = packh2(h[2], h[3]);
                *(uint32_t*)(smem + OFF_A1H + o3) = packh2(h[4], h[5]);
                *(uint32_t*)(smem + OFF_A1H + o4) = packh2(h[6], h[7]);
                *(uint32_t*)(smem + OFF_A1D + o1) = packh2(hd[0], hd[1]);
                *(uint32_t*)(smem + OFF_A1D + o2) = packh2(hd[2], hd[3]);
                *(uint32_t*)(smem + OFF_A1D + o3) = packh2(hd[4], hd[5]);
                *(uint32_t*)(smem + OFF_A1D + o4) = packh2(hd[6], hd[7]);
                *(uint32_t*)(smem + OFF_A1E + o1) = packh2(he[0], he[1]);
                *(uint32_t*)(smem + OFF_A1E + o2) = packh2(he[2], he[3]);
                *(uint32_t*)(smem + OFF_A1E + o3) = packh2(he[4], he[5]);
                *(uint32_t*)(smem + OFF_A1E + o4) = packh2(he[6], he[7]);
            }
        }
        __syncthreads();

        // ================= layer 3 (A1 @ W3, k-outer) fused with layer 4 =================
        {
            float dz[2][8], dp[2][8], dq[2][8];
#pragma unroll
            for (int nt = 0; nt < 2; nt++) {
                const int j0c = nbase + nt * 16 + jc;
                float2 bj = *(const float2*)&smf[IB3 + j0c];
                float2 bj8 = *(const float2*)&smf[IB3 + j0c + 8];
                dz[nt][0] = bj.x; dz[nt][1] = bj.y; dz[nt][2] = bj.x; dz[nt][3] = bj.y;
                dz[nt][4] = bj8.x; dz[nt][5] = bj8.y; dz[nt][6] = bj8.x; dz[nt][7] = bj8.y;
#pragma unroll
                for (int e = 0; e < 8; e++) { dp[nt][e] = 0.f; dq[nt][e] = 0.f; }
            }
            const uint32_t aHb = sb + OFF_A1H + rbA, aDb = sb + OFF_A1D + rbA, aEb = sb + OFF_A1E + rbA;
            const uint32_t wBase = sb + OFF_W3HI + (((uint32_t)nbase + rowB4) << 8);
#pragma unroll
            for (int k = 0; k < 8; k++) {
                const uint32_t oA = (colA + 32u * k) ^ xA;
                const uint32_t oB = (colB4 + 32u * k) ^ xB4;
                uint32_t fa[4], fd[4], fe[4];
                ldsm4(fa, aHb + oA); ldsm4(fd, aDb + oA); ldsm4(fe, aEb + oA);
#pragma unroll
                for (int nt = 0; nt < 2; nt++) {
                    uint32_t bf[4];
                    ldsm4(bf, wBase + ((uint32_t)(nt * 16) << 8) + oB);
                    mma16816(dz[nt], fa, bf); mma16816(dz[nt] + 4, fa, bf + 2);
                    mma16816(dp[nt], fd, bf); mma16816(dp[nt] + 4, fd, bf + 2);
                    mma16816(dq[nt], fe, bf); mma16816(dq[nt] + 4, fe, bf + 2);
                }
            }
            const int nb1 = snb[r1], nb2 = snb[r2];
            const float* w4r1 = g_W4T + nb1 * 128;
            const float* w4r2 = g_W4T + nb2 * 128;
            float pu1 = 0.f, pp1 = 0.f, pq1 = 0.f, pu2 = 0.f, pp2 = 0.f, pq2 = 0.f;
#pragma unroll
            for (int nt = 0; nt < 2; nt++) {
                const int j0c = nbase + nt * 16 + jc;
                float h[8], hd[8], he[8];
#pragma unroll
                for (int e = 0; e < 8; e++) chain(dz[nt][e], dp[nt][e], dq[nt][e], h[e], hd[e], he[e]);
                float2 wa1 = __ldg((const float2*)&w4r1[j0c]);
                float2 wb1 = __ldg((const float2*)&w4r1[j0c + 8]);
                float2 wa2 = __ldg((const float2*)&w4r2[j0c]);
                float2 wb2 = __ldg((const float2*)&w4r2[j0c + 8]);
                pu1 += h[0] * wa1.x + h[1] * wa1.y + h[4] * wb1.x + h[5] * wb1.y;
                pp1 += hd[0] * wa1.x + hd[1] * wa1.y + hd[4] * wb1.x + hd[5] * wb1.y;
                pq1 += he[0] * wa1.x + he[1] * wa1.y + he[4] * wb1.x + he[5] * wb1.y;
                pu2 += h[2] * wa2.x + h[3] * wa2.y + h[6] * wb2.x + h[7] * wb2.y;
                pp2 += hd[2] * wa2.x + hd[3] * wa2.y + hd[6] * wb2.x + hd[7] * wb2.y;
                pq2 += he[2] * wa2.x + he[3] * wa2.y + he[6] * wb2.x + he[7] * wb2.y;
            }
            // reduce across the 4 lanes sharing each row pair
#pragma unroll
            for (int off = 1; off <= 2; off <<= 1) {
                pu1 += __shfl_xor_sync(0xffffffffu, pu1, off);
                pp1 += __shfl_xor_sync(0xffffffffu, pp1, off);
                pq1 += __shfl_xor_sync(0xffffffffu, pq1, off);
                pu2 += __shfl_xor_sync(0xffffffffu, pu2, off);
                pp2 += __shfl_xor_sync(0xffffffffu, pp2, off);
                pq2 += __shfl_xor_sync(0xffffffffu, pq2, off);
            }
            if ((lane & 3) == 0) {
                float dB1 = smf[IDB + r1], dB2 = smf[IDB + r2];
                float c1 = -fmaf(pp1, dB1, pq1 * halfdt);
                float c2 = -fmaf(pp2, dB2, pq2 * halfdt);
                if (j == 0) {
                    c1 += pu1 + (nq == 0 ? smf[IB4 + nb1] : 0.f);
                    c2 += pu2 + (nq == 0 ? smf[IB4 + nb2] : 0.f);
                }
                smf[ISRED + r1 * 4 + nq] = c1;
                smf[ISRED + r2 * 4 + nq] = c2;
            }
        }
        __syncthreads();
        if (tid < TILE)
            acc += (smf[ISRED + tid * 4] + smf[ISRED + tid * 4 + 1])
                 + (smf[ISRED + tid * 4 + 2] + smf[ISRED + tid * 4 + 3]);
        __syncthreads();
    }

    if (tid < TILE) g_partial[grp * B2 + tile * TILE + tid] = acc;
}

__global__ void bsde_final(const float* __restrict__ ss, float* __restrict__ out)
{
    int b = blockIdx.x * 256 + threadIdx.x;
    if (b >= B2) return;
    float u = 0.0f;
#pragma unroll
    for (int g = 0; g < GROUPS; g++) u += g_partial[g * B2 + b];
    out[b] = u;
    float s0 = ss[b * NP1];
    out[B2 + b] = 3.9894228040143274f * expf(-500000.0f * (s0 * s0));
}

extern "C" void kernel_launch(void* const* d_in, const int* in_sizes, int n_in,
                              void* d_out, int out_size)
{
    const float* W1 = (const float*)d_in[0];
    const float* b1 = (const float*)d_in[1];
    const float* W2 = (const float*)d_in[2];
    const float* b2 = (const float*)d_in[3];
    const float* W3 = (const float*)d_in[4];
    const float* b3 = (const float*)d_in[5];
    const float* W4 = (const float*)d_in[6];
    const float* b4 = (const float*)d_in[7];
    const int* sn = (const int*)d_in[8];
    const float* ss = (const float*)d_in[9];
    const float* sdB = (const float*)d_in[10];
    const float* tptr = (const float*)d_in[11];
    float* out = (float*)d_out;

    cudaFuncSetAttribute(bsde_main, cudaFuncAttributeMaxDynamicSharedMemorySize, SMEM_BYTES);

    w4t_init<<<50, 256>>>(W4);
    bsde_main<<<NTILES * GROUPS, THREADS, SMEM_BYTES>>>(W1, b1, W2, b2, W3, b3, b4,
                                                        sn, ss, sdB, tptr);
    bsde_final<<<16, 256>>>(ss, out);
}